// round 16
// baseline (speedup 1.0000x reference)
#include <cuda_runtime.h>
#include <cstdint>
#include <math.h>

static constexpr int BB = 8;
static constexpr int TT = 2048;
static constexpr int CC = 1024;
static constexpr int HSd = 64;

// fp32 scratch for q,k,v (12 MB; __device__ globals, no allocation)
__device__ float g_q[BB * TT * HSd];
__device__ float g_k[BB * TT * HSd];
__device__ float g_v[BB * TT * HSd];

__device__ __forceinline__ float to_tf32(float x) {
    float r;
    asm("cvt.rna.tf32.f32 %0, %1;" : "=f"(r) : "f"(x));
    return r;
}

// mma.sync m16n8k8 tf32: D += A(16x8,row) * B(8x8,col). D/C in-place.
__device__ __forceinline__ void mma_t(float* d, const uint32_t* a,
                                      uint32_t b0, uint32_t b1) {
    asm volatile(
        "mma.sync.aligned.m16n8k8.row.col.f32.tf32.tf32.f32 "
        "{%0,%1,%2,%3}, {%4,%5,%6,%7}, {%8,%9}, {%0,%1,%2,%3};"
        : "+f"(d[0]), "+f"(d[1]), "+f"(d[2]), "+f"(d[3])
        : "r"(a[0]), "r"(a[1]), "r"(a[2]), "r"(a[3]), "r"(b0), "r"(b1));
}

// ===========================================================================
// Kernel 1: fused QKV projection on mma.sync tf32.
// 256 CTAs x 256 thr. CTA tile: 64 rows x 192 cols, K=1024 tiled at 32.
// 8 warps as (2M x 4N); warp tile 32x48 (2 m16 x 6 n8). Double buffered.
// Smem strides: A=36 (frag bank 4r+c), B=200 (frag bank 8k+n) — conflict-free.
// 2 CTAs/SM.
// ===========================================================================
static constexpr int XS_STRIDE = 36;
static constexpr int WS_STRIDE = 200;
static constexpr int XS_ELEMS  = 64 * XS_STRIDE;
static constexpr int WS_ELEMS  = 32 * WS_STRIDE;
static constexpr int PROJ_SMEM = 2 * (XS_ELEMS + WS_ELEMS) * 4;  // 69632 B

__global__ __launch_bounds__(256, 2) void proj_mma(
    const float* __restrict__ x,
    const float* __restrict__ Wq,
    const float* __restrict__ Wk,
    const float* __restrict__ Wv)
{
    extern __shared__ float sm[];
    float* xs = sm;                       // 2 x 64 x 36
    float* ws = sm + 2 * XS_ELEMS;        // 2 x 32 x 200

    const int tid  = threadIdx.x;
    const int lane = tid & 31;
    const int wid  = tid >> 5;
    const int m0   = (wid & 1) * 32;      // warp M offset
    const int n0   = (wid >> 1) * 48;     // warp N offset
    const int row0 = blockIdx.x * 64;

    const float* Wm[3] = {Wq, Wk, Wv};

    float acc[2][6][4];
#pragma unroll
    for (int i = 0; i < 2; i++)
#pragma unroll
        for (int j = 0; j < 6; j++)
#pragma unroll
            for (int c = 0; c < 4; c++) acc[i][j][c] = 0.f;

    float4 pa[2], pb[6];
    const int ar = tid >> 3, aq = tid & 7;  // A: 32 rows/pass x 8 quads

#define LDG_TILE(KT)                                                          \
    do {                                                                      \
        const int kc = (KT) * 32;                                             \
        _Pragma("unroll")                                                     \
        for (int p = 0; p < 2; p++)                                           \
            pa[p] = *(const float4*)&x[(size_t)(row0 + ar + 32 * p) * CC      \
                                       + kc + aq * 4];                        \
        _Pragma("unroll")                                                     \
        for (int p = 0; p < 6; p++) {                                         \
            int f = tid * 4 + 1024 * p;                                       \
            int kk = f / 192, r = f % 192;                                    \
            int mtx = r >> 6, h = r & 63;                                     \
            pb[p] = *(const float4*)&Wm[mtx][(size_t)(kc + kk) * HSd + h];    \
        }                                                                     \
    } while (0)

#define STS_TILE(BUF)                                                         \
    do {                                                                      \
        float* xb = xs + (BUF) * XS_ELEMS;                                    \
        float* wb = ws + (BUF) * WS_ELEMS;                                    \
        _Pragma("unroll")                                                     \
        for (int p = 0; p < 2; p++) {                                         \
            float4 v = pa[p];                                                 \
            v.x = to_tf32(v.x); v.y = to_tf32(v.y);                           \
            v.z = to_tf32(v.z); v.w = to_tf32(v.w);                           \
            *(float4*)&xb[(ar + 32 * p) * XS_STRIDE + aq * 4] = v;            \
        }                                                                     \
        _Pragma("unroll")                                                     \
        for (int p = 0; p < 6; p++) {                                         \
            int f = tid * 4 + 1024 * p;                                       \
            int kk = f / 192, r = f % 192;                                    \
            float4 v = pb[p];                                                 \
            v.x = to_tf32(v.x); v.y = to_tf32(v.y);                           \
            v.z = to_tf32(v.z); v.w = to_tf32(v.w);                           \
            *(float4*)&wb[kk * WS_STRIDE + r] = v;                            \
        }                                                                     \
    } while (0)

    LDG_TILE(0);
    STS_TILE(0);
    __syncthreads();

    for (int kt = 0; kt < 32; kt++) {
        if (kt < 31) LDG_TILE(kt + 1);

        const float* X = xs + (kt & 1) * XS_ELEMS;
        const float* W = ws + (kt & 1) * WS_ELEMS;

#pragma unroll
        for (int k = 0; k < 4; k++) {
            uint32_t a[2][4];
#pragma unroll
            for (int i = 0; i < 2; i++) {
                int r = m0 + i * 16 + (lane >> 2);
                int c = k * 8 + (lane & 3);
                a[i][0] = __float_as_uint(X[r * XS_STRIDE + c]);
                a[i][1] = __float_as_uint(X[(r + 8) * XS_STRIDE + c]);
                a[i][2] = __float_as_uint(X[r * XS_STRIDE + c + 4]);
                a[i][3] = __float_as_uint(X[(r + 8) * XS_STRIDE + c + 4]);
            }
#pragma unroll
            for (int j = 0; j < 6; j++) {
                int kr = k * 8 + (lane & 3);
                int nc = n0 + j * 8 + (lane >> 2);
                uint32_t b0 = __float_as_uint(W[kr * WS_STRIDE + nc]);
                uint32_t b1 = __float_as_uint(W[(kr + 4) * WS_STRIDE + nc]);
                mma_t(acc[0][j], a[0], b0, b1);
                mma_t(acc[1][j], a[1], b0, b1);
            }
        }

        if (kt < 31) STS_TILE((kt + 1) & 1);
        __syncthreads();
    }

#pragma unroll
    for (int i = 0; i < 2; i++) {
        int row = row0 + m0 + i * 16 + (lane >> 2);
#pragma unroll
        for (int j = 0; j < 6; j++) {
            int n   = n0 + j * 8 + 2 * (lane & 3);
            int mtx = n >> 6, h = n & 63;
            float* dst = (mtx == 0) ? g_q : ((mtx == 1) ? g_k : g_v);
            *(float2*)&dst[(size_t)row * HSd + h] =
                make_float2(acc[i][j][0], acc[i][j][1]);
            *(float2*)&dst[(size_t)(row + 8) * HSd + h] =
                make_float2(acc[i][j][2], acc[i][j][3]);
        }
    }
#undef LDG_TILE
#undef STS_TILE
}

// ===========================================================================
// Kernel 2: causal flash attention on mma.sync tf32.
// CTA: Q-tile 64 rows, KV-tile 64; 4 warps (128 thr), each owns one m16 band
// and the full N=64 -> softmax is quad-shuffles only. 3 CTAs/SM (12 warps).
// 256 CTAs; qtile map y<16 ? 31-2y : 2(y-16) balances co-resident pairs.
// All smem arrays stride 68: fragment bank = 4r+c -> conflict-free.
// ===========================================================================
static constexpr int AST = 68;
static constexpr int ATTN_SMEM = (64 * 4) * AST * 4;  // 69632 B

__global__ __launch_bounds__(128, 3) void attn_mma(float* __restrict__ out)
{
    extern __shared__ float sm[];
    float* Qs = sm;                    // 64 x 68
    float* Ks = Qs + 64 * AST;         // 64 x 68
    float* Vs = Ks + 64 * AST;         // 64 x 68
    float* Ps = Vs + 64 * AST;         // 64 x 68

    const int tid  = threadIdx.x;
    const int lane = tid & 31;
    const int wid  = tid >> 5;          // 0..3
    const int b    = blockIdx.x;
    const int y    = blockIdx.y;        // 0..31
    const int qtile = (y < 16) ? (31 - 2 * y) : (2 * (y - 16));
    const int qr0  = qtile * 64;
    const size_t base = (size_t)b * TT * HSd;

    // load Q tile (tf32-rounded): 64x64, 8 float4/thread
#pragma unroll
    for (int p = 0; p < 8; p++) {
        int f = tid * 4 + 512 * p;
        int r = f >> 6, c = f & 63;
        float4 v = *(const float4*)&g_q[base + (size_t)(qr0 + r) * HSd + c];
        v.x = to_tf32(v.x); v.y = to_tf32(v.y);
        v.z = to_tf32(v.z); v.w = to_tf32(v.w);
        *(float4*)&Qs[r * AST + c] = v;
    }

    float o[8][4];
    float m0s = -1e30f, m1s = -1e30f, l0s = 0.f, l1s = 0.f;
#pragma unroll
    for (int j = 0; j < 8; j++)
#pragma unroll
        for (int c = 0; c < 4; c++) o[j][c] = 0.f;

    const int rlow = qr0 + wid * 16 + (lane >> 2);  // global row (and +8)
    const int nkt  = qtile + 1;

    for (int kt = 0; kt < nkt; kt++) {
        __syncthreads();
#pragma unroll
        for (int p = 0; p < 8; p++) {
            int f = tid * 4 + 512 * p;
            int r = f >> 6, c = f & 63;
            float4 kv = *(const float4*)&g_k[base + (size_t)(kt * 64 + r) * HSd + c];
            kv.x = to_tf32(kv.x); kv.y = to_tf32(kv.y);
            kv.z = to_tf32(kv.z); kv.w = to_tf32(kv.w);
            *(float4*)&Ks[r * AST + c] = kv;
            float4 vv = *(const float4*)&g_v[base + (size_t)(kt * 64 + r) * HSd + c];
            vv.x = to_tf32(vv.x); vv.y = to_tf32(vv.y);
            vv.z = to_tf32(vv.z); vv.w = to_tf32(vv.w);
            *(float4*)&Vs[r * AST + c] = vv;
        }
        __syncthreads();

        // ---- S = Q K^T ----
        float s[8][4];
#pragma unroll
        for (int j = 0; j < 8; j++)
#pragma unroll
            for (int c = 0; c < 4; c++) s[j][c] = 0.f;

#pragma unroll
        for (int k = 0; k < 8; k++) {
            uint32_t a[4];
            int r = wid * 16 + (lane >> 2);
            int c = k * 8 + (lane & 3);
            a[0] = __float_as_uint(Qs[r * AST + c]);
            a[1] = __float_as_uint(Qs[(r + 8) * AST + c]);
            a[2] = __float_as_uint(Qs[r * AST + c + 4]);
            a[3] = __float_as_uint(Qs[(r + 8) * AST + c + 4]);
#pragma unroll
            for (int j = 0; j < 8; j++) {
                int key = j * 8 + (lane >> 2);
                uint32_t b0 = __float_as_uint(Ks[key * AST + c]);
                uint32_t b1 = __float_as_uint(Ks[key * AST + c + 4]);
                mma_t(s[j], a, b0, b1);
            }
        }

        // ---- scale + causal mask ----
#pragma unroll
        for (int j = 0; j < 8; j++) {
            int col = kt * 64 + j * 8 + 2 * (lane & 3);
            s[j][0] = (col     > rlow    ) ? -1e30f : s[j][0] * 0.03125f;
            s[j][1] = (col + 1 > rlow    ) ? -1e30f : s[j][1] * 0.03125f;
            s[j][2] = (col     > rlow + 8) ? -1e30f : s[j][2] * 0.03125f;
            s[j][3] = (col + 1 > rlow + 8) ? -1e30f : s[j][3] * 0.03125f;
        }

        // ---- online softmax (quad reductions) ----
        float mx0 = -1e30f, mx1 = -1e30f;
#pragma unroll
        for (int j = 0; j < 8; j++) {
            mx0 = fmaxf(mx0, fmaxf(s[j][0], s[j][1]));
            mx1 = fmaxf(mx1, fmaxf(s[j][2], s[j][3]));
        }
#pragma unroll
        for (int off = 1; off <= 2; off <<= 1) {
            mx0 = fmaxf(mx0, __shfl_xor_sync(0xffffffffu, mx0, off));
            mx1 = fmaxf(mx1, __shfl_xor_sync(0xffffffffu, mx1, off));
        }
        float mn0 = fmaxf(m0s, mx0), mn1 = fmaxf(m1s, mx1);
        float c0 = __expf(m0s - mn0), c1 = __expf(m1s - mn1);
        m0s = mn0; m1s = mn1;

        float rs0 = 0.f, rs1 = 0.f;
#pragma unroll
        for (int j = 0; j < 8; j++) {
            s[j][0] = __expf(s[j][0] - mn0);
            s[j][1] = __expf(s[j][1] - mn0);
            s[j][2] = __expf(s[j][2] - mn1);
            s[j][3] = __expf(s[j][3] - mn1);
            rs0 += s[j][0] + s[j][1];
            rs1 += s[j][2] + s[j][3];
        }
#pragma unroll
        for (int off = 1; off <= 2; off <<= 1) {
            rs0 += __shfl_xor_sync(0xffffffffu, rs0, off);
            rs1 += __shfl_xor_sync(0xffffffffu, rs1, off);
        }
        l0s = l0s * c0 + rs0;
        l1s = l1s * c1 + rs1;
#pragma unroll
        for (int j = 0; j < 8; j++) {
            o[j][0] *= c0; o[j][1] *= c0;
            o[j][2] *= c1; o[j][3] *= c1;
        }

        // ---- stage P (own rows only -> warp-local ordering) ----
        {
            int r = wid * 16 + (lane >> 2);
            int cc = 2 * (lane & 3);
#pragma unroll
            for (int j = 0; j < 8; j++) {
                *(float2*)&Ps[r * AST + j * 8 + cc] =
                    make_float2(to_tf32(s[j][0]), to_tf32(s[j][1]));
                *(float2*)&Ps[(r + 8) * AST + j * 8 + cc] =
                    make_float2(to_tf32(s[j][2]), to_tf32(s[j][3]));
            }
        }
        __syncwarp();

        // ---- O += P V ----
#pragma unroll
        for (int k = 0; k < 8; k++) {
            uint32_t a[4];
            int r = wid * 16 + (lane >> 2);
            int c = k * 8 + (lane & 3);
            a[0] = __float_as_uint(Ps[r * AST + c]);
            a[1] = __float_as_uint(Ps[(r + 8) * AST + c]);
            a[2] = __float_as_uint(Ps[r * AST + c + 4]);
            a[3] = __float_as_uint(Ps[(r + 8) * AST + c + 4]);
#pragma unroll
            for (int j = 0; j < 8; j++) {
                int sv = k * 8 + (lane & 3);
                int h  = j * 8 + (lane >> 2);
                uint32_t b0 = __float_as_uint(Vs[sv * AST + h]);
                uint32_t b1 = __float_as_uint(Vs[(sv + 4) * AST + h]);
                mma_t(o[j], a, b0, b1);
            }
        }
    }

    // epilogue
    float inv0 = 1.0f / l0s, inv1 = 1.0f / l1s;
#pragma unroll
    for (int j = 0; j < 8; j++) {
        int col = j * 8 + 2 * (lane & 3);
        *(float2*)&out[base + (size_t)rlow * HSd + col] =
            make_float2(o[j][0] * inv0, o[j][1] * inv0);
        *(float2*)&out[base + (size_t)(rlow + 8) * HSd + col] =
            make_float2(o[j][2] * inv1, o[j][3] * inv1);
    }
}

// ===========================================================================
// Launch. Inputs: x, mask, Wq, Wk, Wv (mask applied analytically).
// ===========================================================================
extern "C" void kernel_launch(void* const* d_in, const int* in_sizes, int n_in,
                              void* d_out, int out_size)
{
    const float* x  = (const float*)d_in[0];
    const float* Wq = (const float*)d_in[2];
    const float* Wk = (const float*)d_in[3];
    const float* Wv = (const float*)d_in[4];
    float* out = (float*)d_out;

    static bool attr_set = false;
    if (!attr_set) {
        cudaFuncSetAttribute(proj_mma,
                             cudaFuncAttributeMaxDynamicSharedMemorySize, PROJ_SMEM);
        cudaFuncSetAttribute(attn_mma,
                             cudaFuncAttributeMaxDynamicSharedMemorySize, ATTN_SMEM);
        attr_set = true;
    }

    proj_mma<<<(BB * TT) / 64, 256, PROJ_SMEM>>>(x, Wq, Wk, Wv);
    attn_mma<<<dim3(BB, TT / 64), 128, ATTN_SMEM>>>(out);
}

// round 17
// speedup vs baseline: 1.2306x; 1.2306x over previous
#include <cuda_runtime.h>
#include <cstdint>
#include <math.h>

static constexpr int BB = 8;
static constexpr int TT = 2048;
static constexpr int CC = 1024;
static constexpr int HSd = 64;

// scratch: q,k,v (12 MB) + split-KV partials (8 MB + 256 KB)
__device__ float g_q[BB * TT * HSd];
__device__ float g_k[BB * TT * HSd];
__device__ float g_v[BB * TT * HSd];
__device__ float g_po0[BB * TT * HSd];
__device__ float g_po1[BB * TT * HSd];
__device__ float2 g_ml0[BB * TT];
__device__ float2 g_ml1[BB * TT];

__device__ __forceinline__ float to_tf32(float x) {
    float r;
    asm("cvt.rna.tf32.f32 %0, %1;" : "=f"(r) : "f"(x));
    return r;
}

// mma.sync m16n8k8 tf32: D += A(16x8,row) * B(8x8,col). D/C in-place.
__device__ __forceinline__ void mma_t(float* d, const uint32_t* a,
                                      uint32_t b0, uint32_t b1) {
    asm volatile(
        "mma.sync.aligned.m16n8k8.row.col.f32.tf32.tf32.f32 "
        "{%0,%1,%2,%3}, {%4,%5,%6,%7}, {%8,%9}, {%0,%1,%2,%3};"
        : "+f"(d[0]), "+f"(d[1]), "+f"(d[2]), "+f"(d[3])
        : "r"(a[0]), "r"(a[1]), "r"(a[2]), "r"(a[3]), "r"(b0), "r"(b1));
}

// ===========================================================================
// Kernel 1: fused QKV projection on mma.sync tf32.
// Grid (128, 2) x 256 thr. CTA tile: 128 rows x 96 cols (col half =
// blockIdx.y), K=1024 tiled at 32. 8 warps as (4M x 2N); warp tile 32x48.
// Double buffered. Strides: A=36 (bank 4r+c), B=104 (bank 8k+n) — clean.
// 2 CTAs/SM.
// ===========================================================================
static constexpr int XS_STRIDE = 36;
static constexpr int WS_STRIDE = 104;
static constexpr int XS_ELEMS  = 128 * XS_STRIDE;
static constexpr int WS_ELEMS  = 32 * WS_STRIDE;
static constexpr int PROJ_SMEM = 2 * (XS_ELEMS + WS_ELEMS) * 4;  // 63488 B

__global__ __launch_bounds__(256, 2) void proj_mma(
    const float* __restrict__ x,
    const float* __restrict__ Wq,
    const float* __restrict__ Wk,
    const float* __restrict__ Wv)
{
    extern __shared__ float sm[];
    float* xs = sm;                       // 2 x 128 x 36
    float* ws = sm + 2 * XS_ELEMS;        // 2 x 32 x 104

    const int tid  = threadIdx.x;
    const int lane = tid & 31;
    const int wid  = tid >> 5;
    const int m0   = (wid & 3) * 32;      // warp M offset
    const int n0   = (wid >> 2) * 48;     // warp N offset (within 96)
    const int row0 = blockIdx.x * 128;
    const int col0 = blockIdx.y * 96;     // global col of this half

    const float* Wm[3] = {Wq, Wk, Wv};

    float acc[2][6][4];
#pragma unroll
    for (int i = 0; i < 2; i++)
#pragma unroll
        for (int j = 0; j < 6; j++)
#pragma unroll
            for (int c = 0; c < 4; c++) acc[i][j][c] = 0.f;

    float4 pa[4], pb[3];
    const int ar = tid >> 3, aq = tid & 7;  // A: 32 rows/pass x 8 quads

#define LDG_TILE(KT)                                                          \
    do {                                                                      \
        const int kc = (KT) * 32;                                             \
        _Pragma("unroll")                                                     \
        for (int p = 0; p < 4; p++)                                           \
            pa[p] = *(const float4*)&x[(size_t)(row0 + ar + 32 * p) * CC      \
                                       + kc + aq * 4];                        \
        _Pragma("unroll")                                                     \
        for (int p = 0; p < 3; p++) {                                         \
            int f = tid * 4 + 1024 * p;                                       \
            int kk = f / 96, r = f % 96;                                      \
            int col = col0 + r;                                               \
            int mtx = col >> 6, h = col & 63;                                 \
            pb[p] = *(const float4*)&Wm[mtx][(size_t)(kc + kk) * HSd + h];    \
        }                                                                     \
    } while (0)

#define STS_TILE(BUF)                                                         \
    do {                                                                      \
        float* xb = xs + (BUF) * XS_ELEMS;                                    \
        float* wb = ws + (BUF) * WS_ELEMS;                                    \
        _Pragma("unroll")                                                     \
        for (int p = 0; p < 4; p++) {                                         \
            float4 v = pa[p];                                                 \
            v.x = to_tf32(v.x); v.y = to_tf32(v.y);                           \
            v.z = to_tf32(v.z); v.w = to_tf32(v.w);                           \
            *(float4*)&xb[(ar + 32 * p) * XS_STRIDE + aq * 4] = v;            \
        }                                                                     \
        _Pragma("unroll")                                                     \
        for (int p = 0; p < 3; p++) {                                         \
            int f = tid * 4 + 1024 * p;                                       \
            int kk = f / 96, r = f % 96;                                      \
            float4 v = pb[p];                                                 \
            v.x = to_tf32(v.x); v.y = to_tf32(v.y);                           \
            v.z = to_tf32(v.z); v.w = to_tf32(v.w);                           \
            *(float4*)&wb[kk * WS_STRIDE + r] = v;                            \
        }                                                                     \
    } while (0)

    LDG_TILE(0);
    STS_TILE(0);
    __syncthreads();

    for (int kt = 0; kt < 32; kt++) {
        if (kt < 31) LDG_TILE(kt + 1);

        const float* X = xs + (kt & 1) * XS_ELEMS;
        const float* W = ws + (kt & 1) * WS_ELEMS;

#pragma unroll
        for (int k = 0; k < 4; k++) {
            uint32_t a[2][4];
#pragma unroll
            for (int i = 0; i < 2; i++) {
                int r = m0 + i * 16 + (lane >> 2);
                int c = k * 8 + (lane & 3);
                a[i][0] = __float_as_uint(X[r * XS_STRIDE + c]);
                a[i][1] = __float_as_uint(X[(r + 8) * XS_STRIDE + c]);
                a[i][2] = __float_as_uint(X[r * XS_STRIDE + c + 4]);
                a[i][3] = __float_as_uint(X[(r + 8) * XS_STRIDE + c + 4]);
            }
#pragma unroll
            for (int j = 0; j < 6; j++) {
                int kr = k * 8 + (lane & 3);
                int nc = n0 + j * 8 + (lane >> 2);
                uint32_t b0 = __float_as_uint(W[kr * WS_STRIDE + nc]);
                uint32_t b1 = __float_as_uint(W[(kr + 4) * WS_STRIDE + nc]);
                mma_t(acc[0][j], a[0], b0, b1);
                mma_t(acc[1][j], a[1], b0, b1);
            }
        }

        if (kt < 31) STS_TILE((kt + 1) & 1);
        __syncthreads();
    }

#pragma unroll
    for (int i = 0; i < 2; i++) {
        int row = row0 + m0 + i * 16 + (lane >> 2);
#pragma unroll
        for (int j = 0; j < 6; j++) {
            int col = col0 + n0 + j * 8 + 2 * (lane & 3);
            int mtx = col >> 6, h = col & 63;
            float* dst = (mtx == 0) ? g_q : ((mtx == 1) ? g_k : g_v);
            *(float2*)&dst[(size_t)row * HSd + h] =
                make_float2(acc[i][j][0], acc[i][j][1]);
            *(float2*)&dst[(size_t)(row + 8) * HSd + h] =
                make_float2(acc[i][j][2], acc[i][j][3]);
        }
    }
#undef LDG_TILE
#undef STS_TILE
}

// ===========================================================================
// Kernel 2: split-KV causal flash attention on mma.sync tf32.
// Grid (B, 64): qtile = 31 - (y>>1) (heavy first), s = y&1 selects KV half.
// Each CTA: Q-tile 64 rows, 4 warps; writes UNNORMALIZED partial O + (m,l).
// Q fragments hoisted to registers (staged via Ps). 3 CTAs/SM.
// ===========================================================================
static constexpr int AST = 68;
static constexpr int ATTN_SMEM = (64 * 3) * AST * 4;  // 52224 B

__global__ __launch_bounds__(128, 3) void attn_mma()
{
    extern __shared__ float sm[];
    float* Ks = sm;                    // 64 x 68
    float* Vs = Ks + 64 * AST;         // 64 x 68
    float* Ps = Vs + 64 * AST;         // 64 x 68 (also stages Q)

    const int tid  = threadIdx.x;
    const int lane = tid & 31;
    const int wid  = tid >> 5;          // 0..3
    const int b    = blockIdx.x;
    const int y    = blockIdx.y;        // 0..63
    const int qtile = 31 - (y >> 1);
    const int s    = y & 1;
    const int qr0  = qtile * 64;
    const size_t base = (size_t)b * TT * HSd;

    const int h2   = (qtile + 2) >> 1;            // ceil((qtile+1)/2)
    const int kt0  = s ? h2 : 0;
    const int kt1  = s ? qtile + 1 : h2;

    float* PO  = s ? g_po1 : g_po0;
    float2* ML = s ? g_ml1 : g_ml0;

    // ---- stage Q into Ps, then hoist fragments to registers ----
#pragma unroll
    for (int p = 0; p < 8; p++) {
        int f = tid * 4 + 512 * p;
        int r = f >> 6, c = f & 63;
        float4 v = *(const float4*)&g_q[base + (size_t)(qr0 + r) * HSd + c];
        v.x = to_tf32(v.x); v.y = to_tf32(v.y);
        v.z = to_tf32(v.z); v.w = to_tf32(v.w);
        *(float4*)&Ps[r * AST + c] = v;
    }
    __syncthreads();

    uint32_t qf[8][4];
    {
        int r = wid * 16 + (lane >> 2);
#pragma unroll
        for (int k = 0; k < 8; k++) {
            int c = k * 8 + (lane & 3);
            qf[k][0] = __float_as_uint(Ps[r * AST + c]);
            qf[k][1] = __float_as_uint(Ps[(r + 8) * AST + c]);
            qf[k][2] = __float_as_uint(Ps[r * AST + c + 4]);
            qf[k][3] = __float_as_uint(Ps[(r + 8) * AST + c + 4]);
        }
    }

    float o[8][4];
    float m0s = -1e30f, m1s = -1e30f, l0s = 0.f, l1s = 0.f;
#pragma unroll
    for (int j = 0; j < 8; j++)
#pragma unroll
        for (int c = 0; c < 4; c++) o[j][c] = 0.f;

    const int rlow = qr0 + wid * 16 + (lane >> 2);  // global row (and +8)

    for (int kt = kt0; kt < kt1; kt++) {
        __syncthreads();
#pragma unroll
        for (int p = 0; p < 8; p++) {
            int f = tid * 4 + 512 * p;
            int r = f >> 6, c = f & 63;
            float4 kv = *(const float4*)&g_k[base + (size_t)(kt * 64 + r) * HSd + c];
            kv.x = to_tf32(kv.x); kv.y = to_tf32(kv.y);
            kv.z = to_tf32(kv.z); kv.w = to_tf32(kv.w);
            *(float4*)&Ks[r * AST + c] = kv;
            float4 vv = *(const float4*)&g_v[base + (size_t)(kt * 64 + r) * HSd + c];
            vv.x = to_tf32(vv.x); vv.y = to_tf32(vv.y);
            vv.z = to_tf32(vv.z); vv.w = to_tf32(vv.w);
            *(float4*)&Vs[r * AST + c] = vv;
        }
        __syncthreads();

        // ---- S = Q K^T ----
        float sc[8][4];
#pragma unroll
        for (int j = 0; j < 8; j++)
#pragma unroll
            for (int c = 0; c < 4; c++) sc[j][c] = 0.f;

#pragma unroll
        for (int k = 0; k < 8; k++) {
            int c = k * 8 + (lane & 3);
#pragma unroll
            for (int j = 0; j < 8; j++) {
                int key = j * 8 + (lane >> 2);
                uint32_t b0 = __float_as_uint(Ks[key * AST + c]);
                uint32_t b1 = __float_as_uint(Ks[key * AST + c + 4]);
                mma_t(sc[j], qf[k], b0, b1);
            }
        }

        // ---- scale (+ causal mask only on diagonal tile) ----
        if (kt == qtile) {
#pragma unroll
            for (int j = 0; j < 8; j++) {
                int col = kt * 64 + j * 8 + 2 * (lane & 3);
                sc[j][0] = (col     > rlow    ) ? -1e30f : sc[j][0] * 0.03125f;
                sc[j][1] = (col + 1 > rlow    ) ? -1e30f : sc[j][1] * 0.03125f;
                sc[j][2] = (col     > rlow + 8) ? -1e30f : sc[j][2] * 0.03125f;
                sc[j][3] = (col + 1 > rlow + 8) ? -1e30f : sc[j][3] * 0.03125f;
            }
        } else {
#pragma unroll
            for (int j = 0; j < 8; j++)
#pragma unroll
                for (int c = 0; c < 4; c++) sc[j][c] *= 0.03125f;
        }

        // ---- online softmax (quad reductions) ----
        float mx0 = -1e30f, mx1 = -1e30f;
#pragma unroll
        for (int j = 0; j < 8; j++) {
            mx0 = fmaxf(mx0, fmaxf(sc[j][0], sc[j][1]));
            mx1 = fmaxf(mx1, fmaxf(sc[j][2], sc[j][3]));
        }
#pragma unroll
        for (int off = 1; off <= 2; off <<= 1) {
            mx0 = fmaxf(mx0, __shfl_xor_sync(0xffffffffu, mx0, off));
            mx1 = fmaxf(mx1, __shfl_xor_sync(0xffffffffu, mx1, off));
        }
        float mn0 = fmaxf(m0s, mx0), mn1 = fmaxf(m1s, mx1);
        float c0 = __expf(m0s - mn0), c1 = __expf(m1s - mn1);
        m0s = mn0; m1s = mn1;

        float rs0 = 0.f, rs1 = 0.f;
#pragma unroll
        for (int j = 0; j < 8; j++) {
            sc[j][0] = __expf(sc[j][0] - mn0);
            sc[j][1] = __expf(sc[j][1] - mn0);
            sc[j][2] = __expf(sc[j][2] - mn1);
            sc[j][3] = __expf(sc[j][3] - mn1);
            rs0 += sc[j][0] + sc[j][1];
            rs1 += sc[j][2] + sc[j][3];
        }
#pragma unroll
        for (int off = 1; off <= 2; off <<= 1) {
            rs0 += __shfl_xor_sync(0xffffffffu, rs0, off);
            rs1 += __shfl_xor_sync(0xffffffffu, rs1, off);
        }
        l0s = l0s * c0 + rs0;
        l1s = l1s * c1 + rs1;
#pragma unroll
        for (int j = 0; j < 8; j++) {
            o[j][0] *= c0; o[j][1] *= c0;
            o[j][2] *= c1; o[j][3] *= c1;
        }

        // ---- stage P (own rows only -> warp-local ordering) ----
        {
            int r = wid * 16 + (lane >> 2);
            int cc = 2 * (lane & 3);
#pragma unroll
            for (int j = 0; j < 8; j++) {
                *(float2*)&Ps[r * AST + j * 8 + cc] =
                    make_float2(to_tf32(sc[j][0]), to_tf32(sc[j][1]));
                *(float2*)&Ps[(r + 8) * AST + j * 8 + cc] =
                    make_float2(to_tf32(sc[j][2]), to_tf32(sc[j][3]));
            }
        }
        __syncwarp();

        // ---- O += P V ----
#pragma unroll
        for (int k = 0; k < 8; k++) {
            uint32_t a[4];
            int r = wid * 16 + (lane >> 2);
            int c = k * 8 + (lane & 3);
            a[0] = __float_as_uint(Ps[r * AST + c]);
            a[1] = __float_as_uint(Ps[(r + 8) * AST + c]);
            a[2] = __float_as_uint(Ps[r * AST + c + 4]);
            a[3] = __float_as_uint(Ps[(r + 8) * AST + c + 4]);
#pragma unroll
            for (int j = 0; j < 8; j++) {
                int sv = k * 8 + (lane & 3);
                int hh = j * 8 + (lane >> 2);
                uint32_t b0 = __float_as_uint(Vs[sv * AST + hh]);
                uint32_t b1 = __float_as_uint(Vs[(sv + 4) * AST + hh]);
                mma_t(o[j], a, b0, b1);
            }
        }
    }

    // ---- epilogue: unnormalized partial O + (m,l) ----
#pragma unroll
    for (int j = 0; j < 8; j++) {
        int col = j * 8 + 2 * (lane & 3);
        *(float2*)&PO[base + (size_t)rlow * HSd + col] =
            make_float2(o[j][0], o[j][1]);
        *(float2*)&PO[base + (size_t)(rlow + 8) * HSd + col] =
            make_float2(o[j][2], o[j][3]);
    }
    if ((lane & 3) == 0) {
        ML[b * TT + rlow]     = make_float2(m0s, l0s);
        ML[b * TT + rlow + 8] = make_float2(m1s, l1s);
    }
}

// ===========================================================================
// Kernel 3: merge the two KV-split partials.  256 blocks x 256 thr;
// block = 64 rows, 4 threads/row, 16 cols (4 float4) each.
// ===========================================================================
__global__ __launch_bounds__(256) void merge_k(float* __restrict__ out)
{
    const int tid = threadIdx.x;
    const int row = blockIdx.x * 64 + (tid >> 2);   // 0..16383
    const int c0  = (tid & 3) * 16;

    float2 ml0 = g_ml0[row], ml1 = g_ml1[row];
    float m  = fmaxf(ml0.x, ml1.x);
    float w0 = __expf(ml0.x - m), w1 = __expf(ml1.x - m);
    float inv = 1.0f / (ml0.y * w0 + ml1.y * w1);
    w0 *= inv; w1 *= inv;

    const size_t off = (size_t)row * HSd + c0;
#pragma unroll
    for (int q = 0; q < 4; q++) {
        float4 a = *(const float4*)&g_po0[off + q * 4];
        float4 bq = *(const float4*)&g_po1[off + q * 4];
        float4 r;
        r.x = a.x * w0 + bq.x * w1;
        r.y = a.y * w0 + bq.y * w1;
        r.z = a.z * w0 + bq.z * w1;
        r.w = a.w * w0 + bq.w * w1;
        *(float4*)&out[off + q * 4] = r;
    }
}

// ===========================================================================
// Launch. Inputs: x, mask, Wq, Wk, Wv (mask applied analytically).
// ===========================================================================
extern "C" void kernel_launch(void* const* d_in, const int* in_sizes, int n_in,
                              void* d_out, int out_size)
{
    const float* x  = (const float*)d_in[0];
    const float* Wq = (const float*)d_in[2];
    const float* Wk = (const float*)d_in[3];
    const float* Wv = (const float*)d_in[4];
    float* out = (float*)d_out;

    static bool attr_set = false;
    if (!attr_set) {
        cudaFuncSetAttribute(proj_mma,
                             cudaFuncAttributeMaxDynamicSharedMemorySize, PROJ_SMEM);
        cudaFuncSetAttribute(attn_mma,
                             cudaFuncAttributeMaxDynamicSharedMemorySize, ATTN_SMEM);
        attr_set = true;
    }

    proj_mma<<<dim3((BB * TT) / 128, 2), 256, PROJ_SMEM>>>(x, Wq, Wk, Wv);
    attn_mma<<<dim3(BB, 64), 128, ATTN_SMEM>>>();
    merge_k<<<(BB * TT) / 64, 256>>>(out);
}